// round 16
// baseline (speedup 1.0000x reference)
#include <cuda_runtime.h>
#include <math.h>

// ---------------- problem constants (B=1, D=16, H=64, W=64) ----------------
#define DIMC    192
#define HEADS   6
#define HD      32
#define NWTOK   256        // tokens per window
#define NWIN    256        // number of windows
#define NTOK    65536      // total tokens
#define HIDDEN  768
#define RANK1   384
#define RANK2   96
#define QSCALE  0.17677669529663687f   // 32^-0.5

// ---------------- scratch (device globals; no runtime allocation) ----------
__device__ float g_xw[(size_t)NTOK * DIMC];          // LN1 out, windowed layout
__device__ float g_qkv[(size_t)NTOK * 3 * DIMC];     // qkv windowed
__device__ float g_att[(size_t)NTOK * DIMC];         // attention out windowed
__device__ float g_x1[(size_t)NTOK * DIMC];          // residual-1 result, token layout
__device__ float g_ln2[(size_t)NTOK * DIMC];
__device__ float g_t1[(size_t)NTOK * RANK1];
__device__ float g_hid[(size_t)NTOK * HIDDEN];
__device__ float g_hid2[(size_t)NTOK * HIDDEN];
__device__ float g_t2[(size_t)NTOK * RANK2];
__device__ float g_bias[HEADS * NWTOK * NWTOK];      // expanded rel-pos bias
__device__ float g_wT[27 * HIDDEN];                  // conv weights [tap][c]

// ---------------- helpers ----------------
__device__ __forceinline__ float dot4(const float4 a, const float4 b) {
    return a.x * b.x + a.y * b.y + a.z * b.z + a.w * b.w;
}
__device__ __forceinline__ void fma4(float4& a, float s, const float4 v) {
    a.x += s * v.x; a.y += s * v.y; a.z += s * v.z; a.w += s * v.w;
}
__device__ __forceinline__ void mul4(float4& a, float s) {
    a.x *= s; a.y *= s; a.z *= s; a.w *= s;
}
__device__ __forceinline__ unsigned f2tf32(float x) {
    unsigned r; asm("cvt.rna.tf32.f32 %0, %1;" : "=r"(r) : "f"(x)); return r;
}
// windowed row index m = wi*256 + t  ->  token index n = d*4096 + h*64 + w
__device__ __forceinline__ int win_to_tok(int m) {
    int wi = m >> 8, t = m & 255;
    int d = ((wi >> 6) << 2) + (t >> 6);
    int h = (((wi >> 3) & 7) << 3) + ((t >> 3) & 7);
    int w = ((wi & 7) << 3) + (t & 7);
    return (d << 12) + (h << 6) + w;
}

#define MMA_TF32(c, a, b) \
    asm volatile("mma.sync.aligned.m16n8k8.row.col.f32.tf32.tf32.f32 " \
        "{%0,%1,%2,%3}, {%4,%5,%6,%7}, {%8,%9}, {%0,%1,%2,%3};" \
        : "+f"((c)[0]), "+f"((c)[1]), "+f"((c)[2]), "+f"((c)[3]) \
        : "r"((a)[0]), "r"((a)[1]), "r"((a)[2]), "r"((a)[3]), \
          "r"((b)[0]), "r"((b)[1]))

// ---------------- LayerNorm (warp per token), optional window remap --------
template <bool REMAP>
__global__ __launch_bounds__(256) void ln_kernel(
    const float* __restrict__ x, const float* __restrict__ g,
    const float* __restrict__ b, float* __restrict__ out)
{
    const int n = (blockIdx.x << 3) + (threadIdx.x >> 5);
    const int lane = threadIdx.x & 31;
    const float* xp = x + (size_t)n * DIMC;
    float v[6];
    float s = 0.f;
#pragma unroll
    for (int e = 0; e < 6; e++) { v[e] = xp[lane + (e << 5)]; s += v[e]; }
#pragma unroll
    for (int o = 16; o > 0; o >>= 1) s += __shfl_xor_sync(0xffffffffu, s, o);
    const float mean = s * (1.f / 192.f);
    float s2 = 0.f;
#pragma unroll
    for (int e = 0; e < 6; e++) { float d = v[e] - mean; s2 += d * d; }
#pragma unroll
    for (int o = 16; o > 0; o >>= 1) s2 += __shfl_xor_sync(0xffffffffu, s2, o);
    const float inv = rsqrtf(s2 * (1.f / 192.f) + 1e-5f);

    int m;
    if (REMAP) {
        int d = n >> 12, h = (n >> 6) & 63, w = n & 63;
        int wi = ((d >> 2) << 6) + ((h >> 3) << 3) + (w >> 3);
        int t  = ((d & 3) << 6) + ((h & 7) << 3) + (w & 7);
        m = (wi << 8) + t;
    } else {
        m = n;
    }
    float* op = out + (size_t)m * DIMC;
#pragma unroll
    for (int e = 0; e < 6; e++) {
        int c = lane + (e << 5);
        op[c] = (v[e] - mean) * inv * g[c] + b[c];
    }
}

// ---------------- expand rel-pos bias: g_bias[h][i][j] ----------------------
__global__ void bias_pre_kernel(const float* __restrict__ rel_bias,
                                float* __restrict__ bm)
{
    int idx = blockIdx.x * 256 + threadIdx.x;
    if (idx >= HEADS * NWTOK * NWTOK) return;
    int hh = idx >> 16;
    int r = idx & 65535;
    int i = r >> 8, j = r & 255;
    int di = i >> 6, hi = (i >> 3) & 7, wi = i & 7;
    int dj = j >> 6, hj = (j >> 3) & 7, wj = j & 7;
    int rel = (di - dj + 3) * 225 + (hi - hj + 7) * 15 + (wi - wj + 7);
    bm[idx] = rel_bias[rel * HEADS + hh];
}

// ---------------- transpose dwconv weights [c][27] -> [tap][c] --------------
__global__ void wtrans_kernel(const float* __restrict__ ws, float* __restrict__ wt)
{
    int i = blockIdx.x * 256 + threadIdx.x;
    if (i < HIDDEN * 27) {
        int c = i / 27, t = i % 27;
        wt[t * HIDDEN + c] = ws[i];
    }
}

// ---------------- tensor-core tf32 GEMM 128x128x16, fused epilogues ---------
// 8 warps, warp tile 64(m) x 32(n), mma.sync.m16n8k8.tf32.
// EPI: 0 plain, 1 +bias, 2 qkv(+bias, scale q cols), 3 proj(+bias, scatter + resid),
//      4 +bias + resid (same layout)
template <int EPI>
__global__ __launch_bounds__(256) void gemm_tc(
    const float* __restrict__ A, const float* __restrict__ B,
    const float* __restrict__ bias, const float* __restrict__ resid,
    float* __restrict__ C, int M, int N, int K)
{
    __shared__ unsigned As[16][132];   // [k][m], tf32 bits
    __shared__ unsigned Bs[16][132];   // [k][n], tf32 bits

    const int tid = threadIdx.x;
    const int wid = tid >> 5, lane = tid & 31;
    const int gid = lane >> 2, tig = lane & 3;
    const int wm = (wid & 1) << 6;     // 0 / 64
    const int wn = (wid >> 1) << 5;    // 0 / 32 / 64 / 96
    const int m0 = blockIdx.y << 7;
    const int n0 = blockIdx.x << 7;

    const int arow = tid >> 2, acol = (tid & 3) << 2;
    const int brow = tid >> 5, bcol = (tid & 31) << 2;

    float acc[4][4][4];
#pragma unroll
    for (int i = 0; i < 4; i++)
#pragma unroll
        for (int j = 0; j < 4; j++)
#pragma unroll
            for (int c = 0; c < 4; c++) acc[i][j][c] = 0.f;

    const float* Ap0 = A + (size_t)(m0 + arow) * K + acol;
    const float* Ap1 = Ap0 + (size_t)64 * K;
    const bool bok = (n0 + bcol) < N;
    const float* Bp = B + (size_t)brow * N + n0 + bcol;

    for (int k0 = 0; k0 < K; k0 += 16) {
        float4 a0 = *(const float4*)(Ap0 + k0);
        float4 a1 = *(const float4*)(Ap1 + k0);
        float4 b0 = make_float4(0.f, 0.f, 0.f, 0.f), b1 = b0;
        if (bok) {
            b0 = *(const float4*)(Bp + (size_t)k0 * N);
            b1 = *(const float4*)(Bp + (size_t)(k0 + 8) * N);
        }
        __syncthreads();
        As[acol + 0][arow] = f2tf32(a0.x); As[acol + 1][arow] = f2tf32(a0.y);
        As[acol + 2][arow] = f2tf32(a0.z); As[acol + 3][arow] = f2tf32(a0.w);
        As[acol + 0][arow + 64] = f2tf32(a1.x); As[acol + 1][arow + 64] = f2tf32(a1.y);
        As[acol + 2][arow + 64] = f2tf32(a1.z); As[acol + 3][arow + 64] = f2tf32(a1.w);
        Bs[brow][bcol + 0] = f2tf32(b0.x); Bs[brow][bcol + 1] = f2tf32(b0.y);
        Bs[brow][bcol + 2] = f2tf32(b0.z); Bs[brow][bcol + 3] = f2tf32(b0.w);
        Bs[brow + 8][bcol + 0] = f2tf32(b1.x); Bs[brow + 8][bcol + 1] = f2tf32(b1.y);
        Bs[brow + 8][bcol + 2] = f2tf32(b1.z); Bs[brow + 8][bcol + 3] = f2tf32(b1.w);
        __syncthreads();

#pragma unroll
        for (int ks = 0; ks < 16; ks += 8) {
            unsigned af[4][4], bf[4][2];
#pragma unroll
            for (int mt = 0; mt < 4; mt++) {
                const int m = wm + (mt << 4) + gid;
                af[mt][0] = As[ks + tig][m];
                af[mt][1] = As[ks + tig][m + 8];
                af[mt][2] = As[ks + tig + 4][m];
                af[mt][3] = As[ks + tig + 4][m + 8];
            }
#pragma unroll
            for (int nt = 0; nt < 4; nt++) {
                const int n = wn + (nt << 3) + gid;
                bf[nt][0] = Bs[ks + tig][n];
                bf[nt][1] = Bs[ks + tig + 4][n];
            }
#pragma unroll
            for (int mt = 0; mt < 4; mt++)
#pragma unroll
                for (int nt = 0; nt < 4; nt++)
                    MMA_TF32(acc[mt][nt], af[mt], bf[nt]);
        }
    }

    // epilogue: rows (gid, gid+8), cols (2*tig, 2*tig+1) per 16x8 tile
#pragma unroll
    for (int mt = 0; mt < 4; mt++) {
        const int mr0 = m0 + wm + (mt << 4) + gid;
        const int mr1 = mr0 + 8;
        int t0 = 0, t1 = 0;
        if (EPI == 3) { t0 = win_to_tok(mr0); t1 = win_to_tok(mr1); }
#pragma unroll
        for (int nt = 0; nt < 4; nt++) {
            const int n = n0 + wn + (nt << 3) + (tig << 1);
            if (n >= N) continue;
            float* a = acc[mt][nt];
            float2 v0 = make_float2(a[0], a[1]);
            float2 v1 = make_float2(a[2], a[3]);
            if (EPI == 0) {
                *(float2*)(C + (size_t)mr0 * N + n) = v0;
                *(float2*)(C + (size_t)mr1 * N + n) = v1;
            } else {
                const float2 bb = *(const float2*)(bias + n);
                v0.x += bb.x; v0.y += bb.y; v1.x += bb.x; v1.y += bb.y;
                if (EPI == 1) {
                    *(float2*)(C + (size_t)mr0 * N + n) = v0;
                    *(float2*)(C + (size_t)mr1 * N + n) = v1;
                } else if (EPI == 2) {
                    if (n < DIMC) {
                        v0.x *= QSCALE; v0.y *= QSCALE;
                        v1.x *= QSCALE; v1.y *= QSCALE;
                    }
                    *(float2*)(C + (size_t)mr0 * N + n) = v0;
                    *(float2*)(C + (size_t)mr1 * N + n) = v1;
                } else if (EPI == 3) {
                    const size_t o0 = (size_t)t0 * DIMC + n;
                    const size_t o1 = (size_t)t1 * DIMC + n;
                    const float2 r0 = *(const float2*)(resid + o0);
                    const float2 r1 = *(const float2*)(resid + o1);
                    v0.x += r0.x; v0.y += r0.y; v1.x += r1.x; v1.y += r1.y;
                    *(float2*)(C + o0) = v0;
                    *(float2*)(C + o1) = v1;
                } else {
                    const size_t o0 = (size_t)mr0 * N + n;
                    const size_t o1 = (size_t)mr1 * N + n;
                    const float2 r0 = *(const float2*)(resid + o0);
                    const float2 r1 = *(const float2*)(resid + o1);
                    v0.x += r0.x; v0.y += r0.y; v1.x += r1.x; v1.y += r1.y;
                    *(float2*)(C + o0) = v0;
                    *(float2*)(C + o1) = v1;
                }
            }
        }
    }
}

// ---------------- windowed attention: block per (window, head) --------------
__global__ __launch_bounds__(128) void attn_kernel(
    const float* __restrict__ qkv, const float* __restrict__ bm,
    float* __restrict__ out)
{
    __shared__ float ks[128][36];
    __shared__ float vs[128][36];
    __shared__ int rids[256];

    const int tid = threadIdx.x;
    const int wi = blockIdx.x;
    const int hh = blockIdx.y;
    const int wd = wi >> 6, wh = (wi >> 3) & 7, ww = wi & 7;

#pragma unroll
    for (int e = 0; e < 2; e++) {
        int t = tid + (e << 7);
        int d = (wd << 2) + (t >> 6);
        int h = (wh << 3) + ((t >> 3) & 7);
        int w = (ww << 3) + (t & 7);
        rids[t] = ((((d + 2) & 15) >> 2) << 6) + ((((h + 4) & 63) >> 3) << 3) +
                  (((w + 4) & 63) >> 3);
    }
    __syncthreads();
    const int rid0 = rids[tid];
    const int rid1 = rids[tid + 128];

    const size_t base = (size_t)(wi << 8) * (3 * DIMC) + (size_t)hh * HD;
    float4 q0[8], q1[8];
    {
        const float4* qp0 = (const float4*)(qkv + base + (size_t)tid * (3 * DIMC));
        const float4* qp1 = (const float4*)(qkv + base + (size_t)(tid + 128) * (3 * DIMC));
#pragma unroll
        for (int e = 0; e < 8; e++) { q0[e] = qp0[e]; q1[e] = qp1[e]; }
    }
    const float* bp0 = bm + ((size_t)hh << 16) + ((size_t)tid << 8);
    const float* bp1 = bp0 + (128 << 8);

    float m0 = -1e30f, m1 = -1e30f, l0 = 0.f, l1 = 0.f;
    float4 acc0[8], acc1[8];
#pragma unroll
    for (int e = 0; e < 8; e++) {
        acc0[e] = make_float4(0.f, 0.f, 0.f, 0.f);
        acc1[e] = make_float4(0.f, 0.f, 0.f, 0.f);
    }

    for (int half = 0; half < 2; half++) {
        __syncthreads();
        {
            const int row = (half << 7) + tid;
            const float4* kp = (const float4*)(qkv + base + DIMC + (size_t)row * (3 * DIMC));
            const float4* vp = (const float4*)(qkv + base + 2 * DIMC + (size_t)row * (3 * DIMC));
#pragma unroll
            for (int e = 0; e < 8; e++) {
                *(float4*)&ks[tid][e << 2] = kp[e];
                *(float4*)&vs[tid][e << 2] = vp[e];
            }
        }
        __syncthreads();
        const int joff = half << 7;
#pragma unroll 2
        for (int jj = 0; jj < 128; jj++) {
            const int j = joff + jj;
            const int rj = rids[j];
            const float bb0 = bp0[j];
            const float bb1 = bp1[j];
            float s0 = 0.f, s1 = 0.f;
#pragma unroll
            for (int e = 0; e < 8; e++) {
                float4 k4 = *(const float4*)&ks[jj][e << 2];
                s0 += dot4(q0[e], k4);
                s1 += dot4(q1[e], k4);
            }
            s0 += bb0 + ((rj == rid0) ? 0.f : -100.f);
            s1 += bb1 + ((rj == rid1) ? 0.f : -100.f);

            if (s0 > m0) {
                float c = __expf(m0 - s0);
                m0 = s0; l0 *= c;
#pragma unroll
                for (int e = 0; e < 8; e++) mul4(acc0[e], c);
            }
            if (s1 > m1) {
                float c = __expf(m1 - s1);
                m1 = s1; l1 *= c;
#pragma unroll
                for (int e = 0; e < 8; e++) mul4(acc1[e], c);
            }
            const float p0 = __expf(s0 - m0);
            const float p1 = __expf(s1 - m1);
            l0 += p0; l1 += p1;
#pragma unroll
            for (int e = 0; e < 8; e++) {
                float4 v4 = *(const float4*)&vs[jj][e << 2];
                fma4(acc0[e], p0, v4);
                fma4(acc1[e], p1, v4);
            }
        }
    }

    const float inv0 = 1.f / l0, inv1 = 1.f / l1;
    float* op0 = out + (size_t)((wi << 8) + tid) * DIMC + hh * HD;
    float* op1 = out + (size_t)((wi << 8) + tid + 128) * DIMC + hh * HD;
#pragma unroll
    for (int e = 0; e < 8; e++) {
        float4 o0 = acc0[e]; mul4(o0, inv0);
        float4 o1 = acc1[e]; mul4(o1, inv1);
        *(float4*)(op0 + (e << 2)) = o0;
        *(float4*)(op1 + (e << 2)) = o1;
    }
}

// ---------------- depthwise conv3d 3x3x3 + bias + exact GELU ----------------
__global__ __launch_bounds__(192) void conv_kernel(
    const float* __restrict__ hid, const float* __restrict__ wT,
    const float* __restrict__ wb, float* __restrict__ out)
{
    const int c = threadIdx.x << 2;
    float4 wv[27];
#pragma unroll
    for (int t = 0; t < 27; t++) wv[t] = *(const float4*)(wT + t * HIDDEN + c);
    const float4 bb = *(const float4*)(wb + c);
    const int nbase = blockIdx.x << 4;

    for (int tt = 0; tt < 16; tt++) {
        const int n = nbase + tt;
        const int d = n >> 12, h = (n >> 6) & 63, w = n & 63;
        float4 s = make_float4(0.f, 0.f, 0.f, 0.f);
#pragma unroll
        for (int kd = 0; kd < 3; kd++) {
            int dd = d + kd - 1;
            if ((unsigned)dd >= 16u) continue;
#pragma unroll
            for (int kh = 0; kh < 3; kh++) {
                int h2 = h + kh - 1;
                if ((unsigned)h2 >= 64u) continue;
#pragma unroll
                for (int kw = 0; kw < 3; kw++) {
                    int w2 = w + kw - 1;
                    if ((unsigned)w2 >= 64u) continue;
                    const int t = (kd * 3 + kh) * 3 + kw;
                    const float4 x = *(const float4*)(
                        hid + (size_t)((dd << 12) + (h2 << 6) + w2) * HIDDEN + c);
                    s.x += wv[t].x * x.x; s.y += wv[t].y * x.y;
                    s.z += wv[t].z * x.z; s.w += wv[t].w * x.w;
                }
            }
        }
        s.x += bb.x; s.y += bb.y; s.z += bb.z; s.w += bb.w;
        const float r = 0.70710678118654752440f;
        s.x = 0.5f * s.x * (1.f + erff(s.x * r));
        s.y = 0.5f * s.y * (1.f + erff(s.y * r));
        s.z = 0.5f * s.z * (1.f + erff(s.z * r));
        s.w = 0.5f * s.w * (1.f + erff(s.w * r));
        *(float4*)(out + (size_t)n * HIDDEN + c) = s;
    }
}

// ---------------- launch ----------------
extern "C" void kernel_launch(void* const* d_in, const int* in_sizes, int n_in,
                              void* d_out, int out_size)
{
    const float* x      = (const float*)d_in[0];
    const float* n1g    = (const float*)d_in[1];
    const float* n1b    = (const float*)d_in[2];
    const float* qkv_w  = (const float*)d_in[3];
    const float* qkv_b  = (const float*)d_in[4];
    const float* relb   = (const float*)d_in[5];
    const float* proj_w = (const float*)d_in[6];
    const float* proj_b = (const float*)d_in[7];
    const float* n2g    = (const float*)d_in[8];
    const float* n2b    = (const float*)d_in[9];
    const float* fc1A   = (const float*)d_in[10];
    const float* fc1Bw  = (const float*)d_in[11];
    const float* fc1Bb  = (const float*)d_in[12];
    const float* dww    = (const float*)d_in[13];
    const float* dwb    = (const float*)d_in[14];
    const float* fc2A   = (const float*)d_in[15];
    const float* fc2Bw  = (const float*)d_in[16];
    const float* fc2Bb  = (const float*)d_in[17];
    float* out = (float*)d_out;

    float *xw, *qkv, *att, *x1, *ln2, *t1, *hid, *hid2, *t2, *bm, *wT;
    cudaGetSymbolAddress((void**)&xw,   g_xw);
    cudaGetSymbolAddress((void**)&qkv,  g_qkv);
    cudaGetSymbolAddress((void**)&att,  g_att);
    cudaGetSymbolAddress((void**)&x1,   g_x1);
    cudaGetSymbolAddress((void**)&ln2,  g_ln2);
    cudaGetSymbolAddress((void**)&t1,   g_t1);
    cudaGetSymbolAddress((void**)&hid,  g_hid);
    cudaGetSymbolAddress((void**)&hid2, g_hid2);
    cudaGetSymbolAddress((void**)&t2,   g_t2);
    cudaGetSymbolAddress((void**)&bm,   g_bias);
    cudaGetSymbolAddress((void**)&wT,   g_wT);

    bias_pre_kernel<<<1536, 256>>>(relb, bm);
    wtrans_kernel<<<(HIDDEN * 27 + 255) / 256, 256>>>(dww, wT);

    // LN1 + window partition
    ln_kernel<true><<<NTOK / 8, 256>>>(x, n1g, n1b, xw);
    // QKV GEMM (+bias, q scaled)
    gemm_tc<2><<<dim3(5, 512), 256>>>(xw, qkv_w, qkv_b, nullptr, qkv,
                                      NTOK, 3 * DIMC, DIMC);
    // attention
    attn_kernel<<<dim3(NWIN, HEADS), 128>>>(qkv, bm, att);
    // proj GEMM (+bias, un-window scatter, +shortcut residual)
    gemm_tc<3><<<dim3(2, 512), 256>>>(att, proj_w, proj_b, x, x1,
                                      NTOK, DIMC, DIMC);
    // LN2
    ln_kernel<false><<<NTOK / 8, 256>>>(x1, n2g, n2b, ln2);
    // fc1: low-rank A then B(+bias)
    gemm_tc<0><<<dim3(3, 512), 256>>>(ln2, fc1A, nullptr, nullptr, t1,
                                      NTOK, RANK1, DIMC);
    gemm_tc<1><<<dim3(6, 512), 256>>>(t1, fc1Bw, fc1Bb, nullptr, hid,
                                      NTOK, HIDDEN, RANK1);
    // depthwise conv3d + bias + GELU
    conv_kernel<<<NTOK / 16, 192>>>(hid, wT, dwb, hid2);
    // fc2: low-rank A then B(+bias, +residual x1) -> final output
    gemm_tc<0><<<dim3(1, 512), 256>>>(hid2, fc2A, nullptr, nullptr, t2,
                                      NTOK, RANK2, HIDDEN);
    gemm_tc<4><<<dim3(2, 512), 256>>>(t2, fc2Bw, fc2Bb, x1, out,
                                      NTOK, DIMC, RANK2);
}

// round 17
// speedup vs baseline: 1.6055x; 1.6055x over previous
#include <cuda_runtime.h>
#include <math.h>

// ---------------- problem constants (B=1, D=16, H=64, W=64) ----------------
#define DIMC    192
#define HEADS   6
#define HD      32
#define NWTOK   256
#define NWIN    256
#define NTOK    65536
#define HIDDEN  768
#define RANK1   384
#define RANK2   96
#define QSCALE  0.17677669529663687f

// ---------------- scratch ----------------
__device__ float g_xw[(size_t)NTOK * DIMC];
__device__ float g_qkv[(size_t)NTOK * 3 * DIMC];
__device__ float g_att[(size_t)NTOK * DIMC];
__device__ float g_x1[(size_t)NTOK * DIMC];
__device__ float g_ln2[(size_t)NTOK * DIMC];
__device__ float g_t1[(size_t)NTOK * RANK1];
__device__ float g_hid[(size_t)NTOK * HIDDEN];
__device__ float g_hid2[(size_t)NTOK * HIDDEN];
__device__ float g_t2[(size_t)NTOK * RANK2];
__device__ float g_bias[HEADS * NWTOK * NWTOK];
__device__ float g_wT[27 * HIDDEN];

// ---------------- helpers ----------------
__device__ __forceinline__ int win_to_tok(int m) {
    int wi = m >> 8, t = m & 255;
    int d = ((wi >> 6) << 2) + (t >> 6);
    int h = (((wi >> 3) & 7) << 3) + ((t >> 3) & 7);
    int w = ((wi & 7) << 3) + (t & 7);
    return (d << 12) + (h << 6) + w;
}

#define MMA_TF32(c, a, b) \
    asm volatile("mma.sync.aligned.m16n8k8.row.col.f32.tf32.tf32.f32 " \
        "{%0,%1,%2,%3}, {%4,%5,%6,%7}, {%8,%9}, {%0,%1,%2,%3};" \
        : "+f"((c)[0]), "+f"((c)[1]), "+f"((c)[2]), "+f"((c)[3]) \
        : "r"((a)[0]), "r"((a)[1]), "r"((a)[2]), "r"((a)[3]), \
          "r"((b)[0]), "r"((b)[1]))

__device__ __forceinline__ void cp16(unsigned dst, const float* src, int sz) {
    asm volatile("cp.async.cg.shared.global [%0], [%1], 16, %2;"
                 :: "r"(dst), "l"(src), "r"(sz));
}

// ---------------- LayerNorm (warp per token), optional window remap --------
template <bool REMAP>
__global__ __launch_bounds__(256) void ln_kernel(
    const float* __restrict__ x, const float* __restrict__ g,
    const float* __restrict__ b, float* __restrict__ out)
{
    const int n = (blockIdx.x << 3) + (threadIdx.x >> 5);
    const int lane = threadIdx.x & 31;
    const float* xp = x + (size_t)n * DIMC;
    float v[6];
    float s = 0.f;
#pragma unroll
    for (int e = 0; e < 6; e++) { v[e] = xp[lane + (e << 5)]; s += v[e]; }
#pragma unroll
    for (int o = 16; o > 0; o >>= 1) s += __shfl_xor_sync(0xffffffffu, s, o);
    const float mean = s * (1.f / 192.f);
    float s2 = 0.f;
#pragma unroll
    for (int e = 0; e < 6; e++) { float d = v[e] - mean; s2 += d * d; }
#pragma unroll
    for (int o = 16; o > 0; o >>= 1) s2 += __shfl_xor_sync(0xffffffffu, s2, o);
    const float inv = rsqrtf(s2 * (1.f / 192.f) + 1e-5f);

    int m;
    if (REMAP) {
        int d = n >> 12, h = (n >> 6) & 63, w = n & 63;
        int wi = ((d >> 2) << 6) + ((h >> 3) << 3) + (w >> 3);
        int t  = ((d & 3) << 6) + ((h & 7) << 3) + (w & 7);
        m = (wi << 8) + t;
    } else {
        m = n;
    }
    float* op = out + (size_t)m * DIMC;
#pragma unroll
    for (int e = 0; e < 6; e++) {
        int c = lane + (e << 5);
        op[c] = (v[e] - mean) * inv * g[c] + b[c];
    }
}

// ---------------- expand rel-pos bias ----------------
__global__ void bias_pre_kernel(const float* __restrict__ rel_bias,
                                float* __restrict__ bm)
{
    int idx = blockIdx.x * 256 + threadIdx.x;
    if (idx >= HEADS * NWTOK * NWTOK) return;
    int hh = idx >> 16;
    int r = idx & 65535;
    int i = r >> 8, j = r & 255;
    int di = i >> 6, hi = (i >> 3) & 7, wi = i & 7;
    int dj = j >> 6, hj = (j >> 3) & 7, wj = j & 7;
    int rel = (di - dj + 3) * 225 + (hi - hj + 7) * 15 + (wi - wj + 7);
    bm[idx] = rel_bias[rel * HEADS + hh];
}

// ---------------- transpose dwconv weights ----------------
__global__ void wtrans_kernel(const float* __restrict__ ws, float* __restrict__ wt)
{
    int i = blockIdx.x * 256 + threadIdx.x;
    if (i < HIDDEN * 27) {
        int c = i / 27, t = i % 27;
        wt[t * HIDDEN + c] = ws[i];
    }
}

// ---------------- cp.async-pipelined tf32 GEMM 128x128x16 -------------------
// 3 stages, 8 warps (64x32 warp tile). A smem [m][20], B smem [k][136].
// EPI: 0 plain, 1 +bias, 2 qkv(+bias, scale q cols), 3 proj(scatter+resid),
//      4 +bias + resid
#define A_STG 2560   // 128*20 floats per stage
#define B_STG 2176   // 16*136 floats per stage
#define GEMM_SMEM ((3 * (A_STG + B_STG)) * 4)

template <int EPI>
__global__ __launch_bounds__(256) void gemm_tc(
    const float* __restrict__ A, const float* __restrict__ B,
    const float* __restrict__ bias, const float* __restrict__ resid,
    float* __restrict__ C, int M, int N, int K)
{
    extern __shared__ float smemf[];
    float* Asm = smemf;
    float* Bsm = smemf + 3 * A_STG;
    const unsigned abase = (unsigned)__cvta_generic_to_shared(Asm);
    const unsigned bbase = (unsigned)__cvta_generic_to_shared(Bsm);

    const int tid = threadIdx.x;
    const int wid = tid >> 5, lane = tid & 31;
    const int gid = lane >> 2, tig = lane & 3;
    const int wm = (wid & 1) << 6;
    const int wn = (wid >> 1) << 5;
    const int m0 = blockIdx.y << 7;
    const int n0 = blockIdx.x << 7;
    const int KT = K >> 4;

    float acc[4][4][4];
#pragma unroll
    for (int i = 0; i < 4; i++)
#pragma unroll
        for (int j = 0; j < 4; j++)
#pragma unroll
            for (int c = 0; c < 4; c++) acc[i][j][c] = 0.f;

    auto issue = [&](int kt) {
        const int s = kt % 3;
        const unsigned ab = abase + (unsigned)(s * A_STG * 4);
        const unsigned bb = bbase + (unsigned)(s * B_STG * 4);
#pragma unroll
        for (int e = 0; e < 2; e++) {
            int c = tid + (e << 8);
            int row = c >> 2, seg = (c & 3) << 2;
            cp16(ab + (unsigned)((row * 20 + seg) << 2),
                 A + (size_t)(m0 + row) * K + (kt << 4) + seg, 16);
        }
#pragma unroll
        for (int e = 0; e < 2; e++) {
            int c = tid + (e << 8);
            int row = c >> 5, seg = (c & 31) << 2;
            cp16(bb + (unsigned)((row * 136 + seg) << 2),
                 B + (size_t)((kt << 4) + row) * N + n0 + seg,
                 (n0 + seg) < N ? 16 : 0);
        }
        asm volatile("cp.async.commit_group;");
    };

    issue(0);
    issue(1);

    for (int kt = 0; kt < KT; kt++) {
        asm volatile("cp.async.wait_group 1;");
        __syncthreads();
        const float* As_ = Asm + (kt % 3) * A_STG;
        const float* Bs_ = Bsm + (kt % 3) * B_STG;
#pragma unroll
        for (int kss = 0; kss < 2; kss++) {
            const int kb = kss << 3;
            unsigned af[4][4], bf[4][2];
#pragma unroll
            for (int mt = 0; mt < 4; mt++) {
                const int r = wm + (mt << 4) + gid;
                af[mt][0] = __float_as_uint(As_[r * 20 + kb + tig]);
                af[mt][1] = __float_as_uint(As_[(r + 8) * 20 + kb + tig]);
                af[mt][2] = __float_as_uint(As_[r * 20 + kb + tig + 4]);
                af[mt][3] = __float_as_uint(As_[(r + 8) * 20 + kb + tig + 4]);
            }
#pragma unroll
            for (int nt = 0; nt < 4; nt++) {
                const int n = wn + (nt << 3) + gid;
                bf[nt][0] = __float_as_uint(Bs_[(kb + tig) * 136 + n]);
                bf[nt][1] = __float_as_uint(Bs_[(kb + tig + 4) * 136 + n]);
            }
#pragma unroll
            for (int mt = 0; mt < 4; mt++)
#pragma unroll
                for (int nt = 0; nt < 4; nt++)
                    MMA_TF32(acc[mt][nt], af[mt], bf[nt]);
        }
        if (kt + 2 < KT) issue(kt + 2);
        else asm volatile("cp.async.commit_group;");
    }

    // epilogue: rows (gid, gid+8), cols (2*tig, 2*tig+1) per 16x8 tile
#pragma unroll
    for (int mt = 0; mt < 4; mt++) {
        const int mr0 = m0 + wm + (mt << 4) + gid;
        const int mr1 = mr0 + 8;
        int t0 = 0, t1 = 0;
        if (EPI == 3) { t0 = win_to_tok(mr0); t1 = win_to_tok(mr1); }
#pragma unroll
        for (int nt = 0; nt < 4; nt++) {
            const int n = n0 + wn + (nt << 3) + (tig << 1);
            if (n >= N) continue;
            float* a = acc[mt][nt];
            float2 v0 = make_float2(a[0], a[1]);
            float2 v1 = make_float2(a[2], a[3]);
            if (EPI == 0) {
                *(float2*)(C + (size_t)mr0 * N + n) = v0;
                *(float2*)(C + (size_t)mr1 * N + n) = v1;
            } else {
                const float2 bb = *(const float2*)(bias + n);
                v0.x += bb.x; v0.y += bb.y; v1.x += bb.x; v1.y += bb.y;
                if (EPI == 1) {
                    *(float2*)(C + (size_t)mr0 * N + n) = v0;
                    *(float2*)(C + (size_t)mr1 * N + n) = v1;
                } else if (EPI == 2) {
                    if (n < DIMC) {
                        v0.x *= QSCALE; v0.y *= QSCALE;
                        v1.x *= QSCALE; v1.y *= QSCALE;
                    }
                    *(float2*)(C + (size_t)mr0 * N + n) = v0;
                    *(float2*)(C + (size_t)mr1 * N + n) = v1;
                } else if (EPI == 3) {
                    const size_t o0 = (size_t)t0 * DIMC + n;
                    const size_t o1 = (size_t)t1 * DIMC + n;
                    const float2 r0 = *(const float2*)(resid + o0);
                    const float2 r1 = *(const float2*)(resid + o1);
                    v0.x += r0.x; v0.y += r0.y; v1.x += r1.x; v1.y += r1.y;
                    *(float2*)(C + o0) = v0;
                    *(float2*)(C + o1) = v1;
                } else {
                    const size_t o0 = (size_t)mr0 * N + n;
                    const size_t o1 = (size_t)mr1 * N + n;
                    const float2 r0 = *(const float2*)(resid + o0);
                    const float2 r1 = *(const float2*)(resid + o1);
                    v0.x += r0.x; v0.y += r0.y; v1.x += r1.x; v1.y += r1.y;
                    *(float2*)(C + o0) = v0;
                    *(float2*)(C + o1) = v1;
                }
            }
        }
    }
}

// ---------------- tensor-core flash attention ------------------------------
// block = (window, head), 256 threads / 8 warps, warp owns 32 q rows.
// KV processed in 8 chunks of 32. S = Q K^T and O += P V via mma.tf32.
__global__ __launch_bounds__(256) void attn_tc(
    const float* __restrict__ qkv, const float* __restrict__ bm,
    float* __restrict__ out)
{
    __shared__ float Ks[32][36];           // [kv][hd]
    __shared__ float Vs[32][40];           // [kv][hd]
    __shared__ float Ps[8][32][36];        // per-warp P tile [row][kv]
    __shared__ int rids[256];

    const int tid = threadIdx.x;
    const int wid = tid >> 5, lane = tid & 31;
    const int gid = lane >> 2, tig = lane & 3;
    const int wi = blockIdx.x, hh = blockIdx.y;
    const int wd = wi >> 6, wh = (wi >> 3) & 7, ww = wi & 7;

    {
        int t = tid;
        int d = (wd << 2) + (t >> 6);
        int h = (wh << 3) + ((t >> 3) & 7);
        int w = (ww << 3) + (t & 7);
        rids[t] = ((((d + 2) & 15) >> 2) << 6) + ((((h + 4) & 63) >> 3) << 3) +
                  (((w + 4) & 63) >> 3);
    }
    __syncthreads();

    const size_t base = (size_t)(wi << 8) * (3 * DIMC) + (size_t)hh * HD;
    const int wq = wid << 5;

    // Q fragments in registers (already scaled by QSCALE in qkv gemm)
    unsigned qf[2][4][4];
#pragma unroll
    for (int mt = 0; mt < 2; mt++) {
        const int r0 = wq + (mt << 4) + gid;
        const float* q0 = qkv + base + (size_t)r0 * (3 * DIMC);
        const float* q1 = q0 + (size_t)8 * (3 * DIMC);
#pragma unroll
        for (int ks = 0; ks < 4; ks++) {
            qf[mt][ks][0] = __float_as_uint(q0[(ks << 3) + tig]);
            qf[mt][ks][1] = __float_as_uint(q1[(ks << 3) + tig]);
            qf[mt][ks][2] = __float_as_uint(q0[(ks << 3) + tig + 4]);
            qf[mt][ks][3] = __float_as_uint(q1[(ks << 3) + tig + 4]);
        }
    }
    int ridr[2][2];
#pragma unroll
    for (int mt = 0; mt < 2; mt++) {
        ridr[mt][0] = rids[wq + (mt << 4) + gid];
        ridr[mt][1] = rids[wq + (mt << 4) + 8 + gid];
    }

    float mrow[2][2], lrow[2][2];
    float oacc[2][4][4];
#pragma unroll
    for (int mt = 0; mt < 2; mt++)
#pragma unroll
        for (int hf = 0; hf < 2; hf++) { mrow[mt][hf] = -1e30f; lrow[mt][hf] = 0.f; }
#pragma unroll
    for (int mt = 0; mt < 2; mt++)
#pragma unroll
        for (int nt = 0; nt < 4; nt++)
#pragma unroll
            for (int c = 0; c < 4; c++) oacc[mt][nt][c] = 0.f;

    for (int ch = 0; ch < 8; ch++) {
        const int j0 = ch << 5;
        __syncthreads();
#pragma unroll
        for (int e = 0; e < 4; e++) {
            int idx = tid + (e << 8);
            int kv = idx >> 5, hd = idx & 31;
            const size_t g = base + (size_t)(j0 + kv) * (3 * DIMC) + hd;
            Ks[kv][hd] = qkv[g + DIMC];
            Vs[kv][hd] = qkv[g + 2 * DIMC];
        }
        __syncthreads();

        // ---- S = Q K^T  (K fragment read transposed from Ks[kv][hd]) ----
        float sacc[2][4][4];
#pragma unroll
        for (int mt = 0; mt < 2; mt++)
#pragma unroll
            for (int nt = 0; nt < 4; nt++)
#pragma unroll
                for (int c = 0; c < 4; c++) sacc[mt][nt][c] = 0.f;
#pragma unroll
        for (int ks = 0; ks < 4; ks++) {
            unsigned kb[4][2];
#pragma unroll
            for (int nt = 0; nt < 4; nt++) {
                kb[nt][0] = __float_as_uint(Ks[(nt << 3) + gid][(ks << 3) + tig]);
                kb[nt][1] = __float_as_uint(Ks[(nt << 3) + gid][(ks << 3) + tig + 4]);
            }
#pragma unroll
            for (int mt = 0; mt < 2; mt++)
#pragma unroll
                for (int nt = 0; nt < 4; nt++)
                    MMA_TF32(sacc[mt][nt], qf[mt][ks], kb[nt]);
        }

        // ---- bias + mask + online softmax; write P tile ----
#pragma unroll
        for (int mt = 0; mt < 2; mt++) {
#pragma unroll
            for (int hf = 0; hf < 2; hf++) {
                const int row = wq + (mt << 4) + (hf << 3) + gid;
                const int rr = ridr[mt][hf];
                float sv[8];
#pragma unroll
                for (int nt = 0; nt < 4; nt++) {
                    const int j = j0 + (nt << 3) + (tig << 1);
                    const float2 bb = *(const float2*)(
                        bm + ((size_t)hh << 16) + ((size_t)row << 8) + j);
                    sv[nt * 2 + 0] = sacc[mt][nt][hf * 2 + 0] + bb.x +
                                     ((rids[j] == rr) ? 0.f : -100.f);
                    sv[nt * 2 + 1] = sacc[mt][nt][hf * 2 + 1] + bb.y +
                                     ((rids[j + 1] == rr) ? 0.f : -100.f);
                }
                float cm = sv[0];
#pragma unroll
                for (int e = 1; e < 8; e++) cm = fmaxf(cm, sv[e]);
                cm = fmaxf(cm, __shfl_xor_sync(0xffffffffu, cm, 1));
                cm = fmaxf(cm, __shfl_xor_sync(0xffffffffu, cm, 2));
                const float mold = mrow[mt][hf];
                const float mnew = fmaxf(mold, cm);
                const float alpha = __expf(mold - mnew);
                float psum = 0.f;
#pragma unroll
                for (int e = 0; e < 8; e++) {
                    sv[e] = __expf(sv[e] - mnew);
                    psum += sv[e];
                }
                psum += __shfl_xor_sync(0xffffffffu, psum, 1);
                psum += __shfl_xor_sync(0xffffffffu, psum, 2);
                mrow[mt][hf] = mnew;
                lrow[mt][hf] = lrow[mt][hf] * alpha + psum;
#pragma unroll
                for (int nto = 0; nto < 4; nto++) {
                    oacc[mt][nto][hf * 2 + 0] *= alpha;
                    oacc[mt][nto][hf * 2 + 1] *= alpha;
                }
                const int lr = (mt << 4) + (hf << 3) + gid;
#pragma unroll
                for (int nt = 0; nt < 4; nt++)
                    *(float2*)&Ps[wid][lr][(nt << 3) + (tig << 1)] =
                        make_float2(sv[nt * 2], sv[nt * 2 + 1]);
            }
        }
        __syncwarp();

        // ---- O += P V ----
#pragma unroll
        for (int ks = 0; ks < 4; ks++) {
            unsigned vb[4][2];
#pragma unroll
            for (int nt = 0; nt < 4; nt++) {
                vb[nt][0] = __float_as_uint(Vs[(ks << 3) + tig][(nt << 3) + gid]);
                vb[nt][1] = __float_as_uint(Vs[(ks << 3) + tig + 4][(nt << 3) + gid]);
            }
#pragma unroll
            for (int mt = 0; mt < 2; mt++) {
                unsigned pa[4];
                pa[0] = __float_as_uint(Ps[wid][(mt << 4) + gid][(ks << 3) + tig]);
                pa[1] = __float_as_uint(Ps[wid][(mt << 4) + 8 + gid][(ks << 3) + tig]);
                pa[2] = __float_as_uint(Ps[wid][(mt << 4) + gid][(ks << 3) + tig + 4]);
                pa[3] = __float_as_uint(Ps[wid][(mt << 4) + 8 + gid][(ks << 3) + tig + 4]);
#pragma unroll
                for (int nt = 0; nt < 4; nt++)
                    MMA_TF32(oacc[mt][nt], pa, vb[nt]);
            }
        }
    }

    // ---- write O / l ----
#pragma unroll
    for (int mt = 0; mt < 2; mt++) {
        const float i0 = 1.f / lrow[mt][0];
        const float i1 = 1.f / lrow[mt][1];
        const int r0 = wq + (mt << 4) + gid;
#pragma unroll
        for (int nt = 0; nt < 4; nt++) {
            const int col = hh * HD + (nt << 3) + (tig << 1);
            *(float2*)(out + (size_t)((wi << 8) + r0) * DIMC + col) =
                make_float2(oacc[mt][nt][0] * i0, oacc[mt][nt][1] * i0);
            *(float2*)(out + (size_t)((wi << 8) + r0 + 8) * DIMC + col) =
                make_float2(oacc[mt][nt][2] * i1, oacc[mt][nt][3] * i1);
        }
    }
}

// ---------------- depthwise conv3d 3x3x3 + bias + exact GELU ----------------
__global__ __launch_bounds__(192) void conv_kernel(
    const float* __restrict__ hid, const float* __restrict__ wT,
    const float* __restrict__ wb, float* __restrict__ out)
{
    const int c = threadIdx.x << 2;
    float4 wv[27];
#pragma unroll
    for (int t = 0; t < 27; t++) wv[t] = *(const float4*)(wT + t * HIDDEN + c);
    const float4 bb = *(const float4*)(wb + c);
    const int nbase = blockIdx.x << 4;

    for (int tt = 0; tt < 16; tt++) {
        const int n = nbase + tt;
        const int d = n >> 12, h = (n >> 6) & 63, w = n & 63;
        float4 s = make_float4(0.f, 0.f, 0.f, 0.f);
#pragma unroll
        for (int kd = 0; kd < 3; kd++) {
            int dd = d + kd - 1;
            if ((unsigned)dd >= 16u) continue;
#pragma unroll
            for (int kh = 0; kh < 3; kh++) {
                int h2 = h + kh - 1;
                if ((unsigned)h2 >= 64u) continue;
#pragma unroll
                for (int kw = 0; kw < 3; kw++) {
                    int w2 = w + kw - 1;
                    if ((unsigned)w2 >= 64u) continue;
                    const int t = (kd * 3 + kh) * 3 + kw;
                    const float4 x = *(const float4*)(
                        hid + (size_t)((dd << 12) + (h2 << 6) + w2) * HIDDEN + c);
                    s.x += wv[t].x * x.x; s.y += wv[t].y * x.y;
                    s.z += wv[t].z * x.z; s.w += wv[t].w * x.w;
                }
            }
        }
        s.x += bb.x; s.y += bb.y; s.z += bb.z; s.w += bb.w;
        const float r = 0.70710678118654752440f;
        s.x = 0.5f * s.x * (1.f + erff(s.x * r));
        s.y = 0.5f * s.y * (1.f + erff(s.y * r));
        s.z = 0.5f * s.z * (1.f + erff(s.z * r));
        s.w = 0.5f * s.w * (1.f + erff(s.w * r));
        *(float4*)(out + (size_t)n * HIDDEN + c) = s;
    }
}

// ---------------- launch ----------------
extern "C" void kernel_launch(void* const* d_in, const int* in_sizes, int n_in,
                              void* d_out, int out_size)
{
    const float* x      = (const float*)d_in[0];
    const float* n1g    = (const float*)d_in[1];
    const float* n1b    = (const float*)d_in[2];
    const float* qkv_w  = (const float*)d_in[3];
    const float* qkv_b  = (const float*)d_in[4];
    const float* relb   = (const float*)d_in[5];
    const float* proj_w = (const float*)d_in[6];
    const float* proj_b = (const float*)d_in[7];
    const float* n2g    = (const float*)d_in[8];
    const float* n2b    = (const float*)d_in[9];
    const float* fc1A   = (const float*)d_in[10];
    const float* fc1Bw  = (const float*)d_in[11];
    const float* fc1Bb  = (const float*)d_in[12];
    const float* dww    = (const float*)d_in[13];
    const float* dwb    = (const float*)d_in[14];
    const float* fc2A   = (const float*)d_in[15];
    const float* fc2Bw  = (const float*)d_in[16];
    const float* fc2Bb  = (const float*)d_in[17];
    float* out = (float*)d_out;

    float *xw, *qkv, *att, *x1, *ln2, *t1, *hid, *hid2, *t2, *bm, *wT;
    cudaGetSymbolAddress((void**)&xw,   g_xw);
    cudaGetSymbolAddress((void**)&qkv,  g_qkv);
    cudaGetSymbolAddress((void**)&att,  g_att);
    cudaGetSymbolAddress((void**)&x1,   g_x1);
    cudaGetSymbolAddress((void**)&ln2,  g_ln2);
    cudaGetSymbolAddress((void**)&t1,   g_t1);
    cudaGetSymbolAddress((void**)&hid,  g_hid);
    cudaGetSymbolAddress((void**)&hid2, g_hid2);
    cudaGetSymbolAddress((void**)&t2,   g_t2);
    cudaGetSymbolAddress((void**)&bm,   g_bias);
    cudaGetSymbolAddress((void**)&wT,   g_wT);

    static bool attr_done = false;
    if (!attr_done) {
        cudaFuncSetAttribute(gemm_tc<0>, cudaFuncAttributeMaxDynamicSharedMemorySize, GEMM_SMEM);
        cudaFuncSetAttribute(gemm_tc<1>, cudaFuncAttributeMaxDynamicSharedMemorySize, GEMM_SMEM);
        cudaFuncSetAttribute(gemm_tc<2>, cudaFuncAttributeMaxDynamicSharedMemorySize, GEMM_SMEM);
        cudaFuncSetAttribute(gemm_tc<3>, cudaFuncAttributeMaxDynamicSharedMemorySize, GEMM_SMEM);
        cudaFuncSetAttribute(gemm_tc<4>, cudaFuncAttributeMaxDynamicSharedMemorySize, GEMM_SMEM);
        attr_done = true;
    }

    bias_pre_kernel<<<1536, 256>>>(relb, bm);
    wtrans_kernel<<<(HIDDEN * 27 + 255) / 256, 256>>>(dww, wT);

    // LN1 + window partition
    ln_kernel<true><<<NTOK / 8, 256>>>(x, n1g, n1b, xw);
    // QKV GEMM (+bias, q scaled)
    gemm_tc<2><<<dim3(5, 512), 256, GEMM_SMEM>>>(xw, qkv_w, qkv_b, nullptr, qkv,
                                                 NTOK, 3 * DIMC, DIMC);
    // flash attention (tensor cores)
    attn_tc<<<dim3(NWIN, HEADS), 256>>>(qkv, bm, att);
    // proj GEMM (+bias, un-window scatter, +shortcut residual)
    gemm_tc<3><<<dim3(2, 512), 256, GEMM_SMEM>>>(att, proj_w, proj_b, x, x1,
                                                 NTOK, DIMC, DIMC);
    // LN2
    ln_kernel<false><<<NTOK / 8, 256>>>(x1, n2g, n2b, ln2);
    // fc1: low-rank A then B(+bias)
    gemm_tc<0><<<dim3(3, 512), 256, GEMM_SMEM>>>(ln2, fc1A, nullptr, nullptr, t1,
                                                 NTOK, RANK1, DIMC);
    gemm_tc<1><<<dim3(6, 512), 256, GEMM_SMEM>>>(t1, fc1Bw, fc1Bb, nullptr, hid,
                                                 NTOK, HIDDEN, RANK1);
    // depthwise conv3d + bias + GELU
    conv_kernel<<<NTOK / 16, 192>>>(hid, wT, dwb, hid2);
    // fc2: low-rank A then B(+bias, +residual x1) -> final output
    gemm_tc<0><<<dim3(1, 512), 256, GEMM_SMEM>>>(hid2, fc2A, nullptr, nullptr, t2,
                                                 NTOK, RANK2, HIDDEN);
    gemm_tc<4><<<dim3(2, 512), 256, GEMM_SMEM>>>(t2, fc2Bw, fc2Bb, x1, out,
                                                 NTOK, DIMC, RANK2);
}